// round 2
// baseline (speedup 1.0000x reference)
#include <cuda_runtime.h>

#define NU 100000          // n_users
#define NE 100000          // n_entities
#define NN 200000          // n_nodes
#define C  64              // channels
#define N_HOPS 3
#define NREL1 15           // weight rows (n_rel - 1)
#define NPREF 16           // extra_weight rows

// -------- persistent scratch (static device globals; no allocation) --------
__device__ __align__(16) float g_all[(size_t)NN * C];          // gather source: [users ; entities]
__device__ __align__(16) float g_agg[(size_t)(NE + NN) * C];   // [ent_agg ; node_agg]
__device__ __align__(16) float g_user_new[(size_t)NU * C];
__device__ __align__(16) float g_ent_cnt[NE];

__device__ __forceinline__ void red_add_v4(float* addr, float4 v) {
    asm volatile("red.global.add.v4.f32 [%0], {%1, %2, %3, %4};"
                 :: "l"(addr), "f"(v.x), "f"(v.y), "f"(v.z), "f"(v.w)
                 : "memory");
}

// ---------------------------------------------------------------------------
// init: g_all = [user_emb ; entity_emb]; out.user_res = user_emb;
//       out.node_res = [user_emb ; entity_emb]
// ---------------------------------------------------------------------------
__global__ void init_kernel(const float* __restrict__ user_emb,
                            const float* __restrict__ entity_emb,
                            float* __restrict__ out) {
    const size_t total4 = (size_t)NN * C / 4;
    const size_t nu4    = (size_t)NU * C / 4;
    const size_t nres4  = (size_t)NN * C / 4;   // node_res offset (float4 units)
    float4*       all4 = (float4*)g_all;
    const float4* ue4  = (const float4*)user_emb;
    const float4* ee4  = (const float4*)entity_emb;
    float4*       out4 = (float4*)out;
    for (size_t i = (size_t)blockIdx.x * blockDim.x + threadIdx.x;
         i < total4; i += (size_t)gridDim.x * blockDim.x) {
        float4 v;
        if (i < nu4) { v = ue4[i]; out4[i] = v; }         // user_res init
        else         { v = ee4[i - nu4]; }
        all4[i] = v;
        out4[nres4 + i] = v;                              // node_res init
    }
}

// zero scratch once (norm kernel re-zeros each hop)
__global__ void zero_kernel() {
    const size_t t1 = (size_t)(NE + NN) * C / 4;
    const size_t t2 = t1 + (size_t)NU * C / 4;
    const size_t t3 = t2 + NE / 4;
    const float4 z = make_float4(0.f, 0.f, 0.f, 0.f);
    for (size_t i = (size_t)blockIdx.x * blockDim.x + threadIdx.x;
         i < t3; i += (size_t)gridDim.x * blockDim.x) {
        if      (i < t1) ((float4*)g_agg     )[i]      = z;
        else if (i < t2) ((float4*)g_user_new)[i - t1] = z;
        else             ((float4*)g_ent_cnt )[i - t2] = z;
    }
}

// ---------------------------------------------------------------------------
// merged edge scatter (4 edges per thread, 16 threads per edge)
//   e <  E : g_agg[head]       += g_all[NU+tail] * weight[type-1], cnt[head]+=1
//   e >= E : g_agg[NE + eh]    += g_all[et]      * extra_weight[type]
// ---------------------------------------------------------------------------
__global__ void __launch_bounds__(256) edge_kernel(
    const int* __restrict__ ei,  const int* __restrict__ ety,
    const int* __restrict__ e2i, const int* __restrict__ e2ty,
    const float* __restrict__ w, const float* __restrict__ w2,
    int E, int E2)
{
    __shared__ float sw[(NREL1 + NPREF) * C];
    for (int i = threadIdx.x; i < NREL1 * C; i += blockDim.x) sw[i] = w[i];
    for (int i = threadIdx.x; i < NPREF * C; i += blockDim.x) sw[NREL1 * C + i] = w2[i];
    __syncthreads();

    int tid  = blockIdx.x * blockDim.x + threadIdx.x;
    int g    = tid >> 4;
    int q    = (tid & 15) * 4;
    int base = g * 4;
    int total = E + E2;
    if (base >= total) return;

    int  soff[4], doff[4], woff[4];
    bool valid[4];
    #pragma unroll
    for (int k = 0; k < 4; k++) {
        int e = base + k;
        valid[k] = (e < total);
        soff[k] = 0; doff[k] = 0; woff[k] = 0;
        if (!valid[k]) continue;
        if (e < E) {
            int head = ei[e];
            int tail = ei[E + e];
            int t    = ety[e] - 1;
            soff[k] = NU + tail;
            doff[k] = head;
            woff[k] = t * C;
            if (q == 0) atomicAdd(g_ent_cnt + head, 1.0f);
        } else {
            int e2  = e - E;
            int eh  = e2i[e2];
            int ett = e2i[E2 + e2];
            int t   = e2ty[e2];
            soff[k] = ett;
            doff[k] = NE + eh;
            woff[k] = (NREL1 + t) * C;
        }
    }

    float4 s[4], wv[4];
    #pragma unroll
    for (int k = 0; k < 4; k++) if (valid[k]) {
        s[k]  = *(const float4*)(g_all + (size_t)soff[k] * C + q);
        wv[k] = *(const float4*)(sw + woff[k] + q);
    }
    #pragma unroll
    for (int k = 0; k < 4; k++) if (valid[k]) {
        float4 v = make_float4(s[k].x * wv[k].x, s[k].y * wv[k].y,
                               s[k].z * wv[k].z, s[k].w * wv[k].w);
        red_add_v4(g_agg + (size_t)doff[k] * C + q, v);
    }
}

// ---------------------------------------------------------------------------
// implicit-matrix user aggregation (4 nnz per thread):
//   user_new[r] += (ent_agg[c] / cnt[c]) * val
// ---------------------------------------------------------------------------
__global__ void __launch_bounds__(256) im_kernel(
    const int* __restrict__ im_row, const int* __restrict__ im_col,
    const float* __restrict__ im_val, int NNZ)
{
    int tid  = blockIdx.x * blockDim.x + threadIdx.x;
    int g    = tid >> 4;
    int q    = (tid & 15) * 4;
    int base = g * 4;
    if (base >= NNZ) return;

    int   coff[4], roff[4];
    float sc[4];
    bool  valid[4];
    #pragma unroll
    for (int k = 0; k < 4; k++) {
        int e = base + k;
        valid[k] = (e < NNZ);
        coff[k] = 0; roff[k] = 0; sc[k] = 0.f;
        if (!valid[k]) continue;
        int r = im_row[e];
        int c = im_col[e];
        sc[k]   = im_val[e] / fmaxf(g_ent_cnt[c], 1.0f);
        coff[k] = c;
        roff[k] = r;
    }
    float4 s[4];
    #pragma unroll
    for (int k = 0; k < 4; k++) if (valid[k])
        s[k] = *(const float4*)(g_agg + (size_t)coff[k] * C + q);
    #pragma unroll
    for (int k = 0; k < 4; k++) if (valid[k]) {
        float4 v = make_float4(s[k].x * sc[k], s[k].y * sc[k],
                               s[k].z * sc[k], s[k].w * sc[k]);
        red_add_v4(g_user_new + (size_t)roff[k] * C + q, v);
    }
}

// ---------------------------------------------------------------------------
// merged norm + accumulate + re-zero. One warp per row, float2 per lane.
// rows [0,NE): entity  |  [NE,NE+NN): node  |  [NE+NN,NE+NN+NU): user
// ---------------------------------------------------------------------------
__device__ __forceinline__ float warp_sum(float s) {
    #pragma unroll
    for (int o = 16; o; o >>= 1) s += __shfl_xor_sync(0xffffffffu, s, o);
    return s;
}

__global__ void __launch_bounds__(256) norm_kernel(float* __restrict__ user_res,
                                                   float* __restrict__ node_res,
                                                   float* __restrict__ ent_out) {
    int row  = blockIdx.x * (blockDim.x >> 5) + (threadIdx.x >> 5);
    int lane = threadIdx.x & 31;
    const float2 z2 = make_float2(0.f, 0.f);

    if (row < NE) {
        // entity: l2norm(ent_agg) (count cancels), write gather source + maybe output
        size_t idx = (size_t)row * C + lane * 2;
        float2 v = *(const float2*)(g_agg + idx);
        *(float2*)(g_agg + idx) = z2;
        if (lane == 0) g_ent_cnt[row] = 0.f;
        float s = warp_sum(v.x * v.x + v.y * v.y);
        float inv = 1.0f / fmaxf(sqrtf(s), 1e-12f);
        float2 o = make_float2(v.x * inv, v.y * inv);
        *(float2*)(g_all + (size_t)(NU + row) * C + lane * 2) = o;
        if (ent_out) *(float2*)(ent_out + idx) = o;
    } else if (row < NE + NN) {
        // node: l2norm(node_agg) (count cancels); store user half as gather src
        int r = row - NE;
        size_t aidx = (size_t)row * C + lane * 2;
        float2 v = *(const float2*)(g_agg + aidx);
        *(float2*)(g_agg + aidx) = z2;
        float s = warp_sum(v.x * v.x + v.y * v.y);
        float inv = 1.0f / fmaxf(sqrtf(s), 1e-12f);
        float2 o = make_float2(v.x * inv, v.y * inv);
        size_t ridx = (size_t)r * C + lane * 2;
        if (r < NU) *(float2*)(g_all + ridx) = o;
        float2 acc = *(const float2*)(node_res + ridx);
        acc.x += o.x; acc.y += o.y;
        *(float2*)(node_res + ridx) = acc;
    } else if (row < NE + NN + NU) {
        // user: user_res += l2norm(user_new)
        int r = row - NE - NN;
        size_t idx = (size_t)r * C + lane * 2;
        float2 v = *(const float2*)(g_user_new + idx);
        *(float2*)(g_user_new + idx) = z2;
        float s = warp_sum(v.x * v.x + v.y * v.y);
        float inv = 1.0f / fmaxf(sqrtf(s), 1e-12f);
        float2 acc = *(const float2*)(user_res + idx);
        acc.x += v.x * inv; acc.y += v.y * inv;
        *(float2*)(user_res + idx) = acc;
    }
}

// ---------------------------------------------------------------------------
extern "C" void kernel_launch(void* const* d_in, const int* in_sizes, int n_in,
                              void* d_out, int out_size) {
    const float* user_emb     = (const float*)d_in[0];
    const float* entity_emb   = (const float*)d_in[1];
    const float* weight       = (const float*)d_in[2];
    const float* extra_weight = (const float*)d_in[3];
    const float* im_val       = (const float*)d_in[4];
    const int*   edge_index   = (const int*)d_in[5];
    const int*   edge_type    = (const int*)d_in[6];
    const int*   extra_eidx   = (const int*)d_in[7];
    const int*   extra_etype  = (const int*)d_in[8];
    const int*   im_row       = (const int*)d_in[9];
    const int*   im_col       = (const int*)d_in[10];

    const int E   = in_sizes[6];
    const int E2  = in_sizes[8];
    const int NNZ = in_sizes[4];

    float* out      = (float*)d_out;
    float* user_res = out;                      // [NU, C]
    float* ent_out  = out + (size_t)NU * C;     // [NE, C] final entity_emb
    float* node_res = out + (size_t)NN * C;     // [NN, C]

    init_kernel<<<2048, 256>>>(user_emb, entity_emb, out);
    zero_kernel<<<2048, 256>>>();

    const int total_edges = E + E2;
    const int edge_groups = (total_edges + 3) / 4;
    const int edge_blocks = (edge_groups * 16 + 255) / 256;
    const int im_groups   = (NNZ + 3) / 4;
    const int im_blocks   = (im_groups * 16 + 255) / 256;
    const int norm_rows   = NE + NN + NU;
    const int norm_blocks = (norm_rows + 7) / 8;

    for (int hop = 0; hop < N_HOPS; hop++) {
        edge_kernel<<<edge_blocks, 256>>>(edge_index, edge_type,
                                          extra_eidx, extra_etype,
                                          weight, extra_weight, E, E2);
        im_kernel<<<im_blocks, 256>>>(im_row, im_col, im_val, NNZ);
        norm_kernel<<<norm_blocks, 256>>>(user_res, node_res,
                                          hop == N_HOPS - 1 ? ent_out : nullptr);
    }
}

// round 3
// speedup vs baseline: 1.0376x; 1.0376x over previous
#include <cuda_runtime.h>

#define NU 100000          // n_users
#define NE 100000          // n_entities
#define NN 200000          // n_nodes
#define C  64              // channels
#define N_HOPS 3

// -------- persistent scratch (static device globals; no allocation) --------
__device__ __align__(16) float g_all[(size_t)NN * C];          // gather source: [users ; entities]
__device__ __align__(16) float g_agg[(size_t)(NE + NN) * C];   // [ent_agg ; node_agg]
__device__ __align__(16) float g_user_new[(size_t)NU * C];
__device__ __align__(16) float g_ent_cnt[NE];
__device__ __align__(16) float g_im_scale[1000000];

__device__ __forceinline__ void red_add_v4(float* addr, float4 v) {
    asm volatile("red.global.add.v4.f32 [%0], {%1, %2, %3, %4};"
                 :: "l"(addr), "f"(v.x), "f"(v.y), "f"(v.z), "f"(v.w)
                 : "memory");
}

// ---------------------------------------------------------------------------
// init: g_all = [user_emb ; entity_emb]; out.user_res = user_emb;
//       out.node_res = [user_emb ; entity_emb]; zero all accumulators + cnt
// ---------------------------------------------------------------------------
__global__ void init_kernel(const float* __restrict__ user_emb,
                            const float* __restrict__ entity_emb,
                            float* __restrict__ out) {
    const size_t nn4   = (size_t)NN * C / 4;
    const size_t nu4   = (size_t)NU * C / 4;
    const size_t z1    = (size_t)(NE + NN) * C / 4;          // g_agg
    const size_t z2    = z1 + (size_t)NU * C / 4;            // g_user_new
    const size_t z3    = z2 + NE / 4;                        // g_ent_cnt
    const size_t total = nn4 + z3;
    const float4 z = make_float4(0.f, 0.f, 0.f, 0.f);
    float4*       all4 = (float4*)g_all;
    const float4* ue4  = (const float4*)user_emb;
    const float4* ee4  = (const float4*)entity_emb;
    float4*       out4 = (float4*)out;
    for (size_t i = (size_t)blockIdx.x * blockDim.x + threadIdx.x;
         i < total; i += (size_t)gridDim.x * blockDim.x) {
        if (i < nn4) {
            float4 v;
            if (i < nu4) { v = ue4[i]; out4[i] = v; }        // user_res init
            else         { v = ee4[i - nu4]; }
            all4[i] = v;
            out4[nn4 + i] = v;                               // node_res init
        } else {
            size_t j = i - nn4;
            if      (j < z1) ((float4*)g_agg     )[j]      = z;
            else if (j < z2) ((float4*)g_user_new)[j - z1] = z;
            else             ((float4*)g_ent_cnt )[j - z2] = z;
        }
    }
}

// counts are hop-invariant: compute once
__global__ void cnt_kernel(const int* __restrict__ ei, int E) {
    int e = blockIdx.x * blockDim.x + threadIdx.x;
    if (e < E) atomicAdd(g_ent_cnt + ei[e], 1.0f);
}

// im scale is hop-invariant: scale[e] = im_val[e] / max(cnt[col[e]], 1)
__global__ void scale_kernel(const float* __restrict__ im_val,
                             const int* __restrict__ im_col, int NNZ) {
    int e = blockIdx.x * blockDim.x + threadIdx.x;
    if (e < NNZ)
        g_im_scale[e] = im_val[e] / fmaxf(g_ent_cnt[im_col[e]], 1.0f);
}

// ---------------------------------------------------------------------------
// merged edge scatter (4 edges per thread, 16 threads per edge)
//   e <  E : g_agg[head]    += g_all[NU+tail] * weight[type-1]
//   e >= E : g_agg[NE + eh] += g_all[et]      * extra_weight[type]
// weight tables read via __ldg (tiny, L1-resident)
// ---------------------------------------------------------------------------
__global__ void __launch_bounds__(256) edge_kernel(
    const int* __restrict__ ei,  const int* __restrict__ ety,
    const int* __restrict__ e2i, const int* __restrict__ e2ty,
    const float* __restrict__ w, const float* __restrict__ w2,
    int E, int E2)
{
    int tid  = blockIdx.x * blockDim.x + threadIdx.x;
    int g    = tid >> 4;
    int q    = (tid & 15) * 4;
    int base = g * 4;
    int total = E + E2;
    if (base >= total) return;

    int  soff[4], doff[4];
    const float* wp[4];
    bool valid[4];
    #pragma unroll
    for (int k = 0; k < 4; k++) {
        int e = base + k;
        valid[k] = (e < total);
        soff[k] = 0; doff[k] = 0; wp[k] = w;
        if (!valid[k]) continue;
        if (e < E) {
            soff[k] = NU + ei[E + e];                  // tail
            doff[k] = ei[e];                           // head
            wp[k]   = w + (size_t)(ety[e] - 1) * C;
        } else {
            int e2  = e - E;
            soff[k] = e2i[E2 + e2];                    // et
            doff[k] = NE + e2i[e2];                    // eh
            wp[k]   = w2 + (size_t)e2ty[e2] * C;
        }
    }

    float4 s[4], wv[4];
    #pragma unroll
    for (int k = 0; k < 4; k++) if (valid[k]) {
        s[k]  = *(const float4*)(g_all + (size_t)soff[k] * C + q);
        wv[k] = __ldg((const float4*)(wp[k] + q));
    }
    #pragma unroll
    for (int k = 0; k < 4; k++) if (valid[k]) {
        float4 v = make_float4(s[k].x * wv[k].x, s[k].y * wv[k].y,
                               s[k].z * wv[k].z, s[k].w * wv[k].w);
        red_add_v4(g_agg + (size_t)doff[k] * C + q, v);
    }
}

// ---------------------------------------------------------------------------
// implicit-matrix user aggregation (4 nnz per thread):
//   user_new[r] += ent_agg[c] * precomputed_scale[e]
// ---------------------------------------------------------------------------
__global__ void __launch_bounds__(256) im_kernel(
    const int* __restrict__ im_row, const int* __restrict__ im_col, int NNZ)
{
    int tid  = blockIdx.x * blockDim.x + threadIdx.x;
    int g    = tid >> 4;
    int q    = (tid & 15) * 4;
    int base = g * 4;
    if (base >= NNZ) return;

    int   coff[4], roff[4];
    float sc[4];
    bool  valid[4];
    #pragma unroll
    for (int k = 0; k < 4; k++) {
        int e = base + k;
        valid[k] = (e < NNZ);
        coff[k] = 0; roff[k] = 0; sc[k] = 0.f;
        if (!valid[k]) continue;
        roff[k] = im_row[e];
        coff[k] = im_col[e];
        sc[k]   = g_im_scale[e];
    }
    float4 s[4];
    #pragma unroll
    for (int k = 0; k < 4; k++) if (valid[k])
        s[k] = *(const float4*)(g_agg + (size_t)coff[k] * C + q);
    #pragma unroll
    for (int k = 0; k < 4; k++) if (valid[k]) {
        float4 v = make_float4(s[k].x * sc[k], s[k].y * sc[k],
                               s[k].z * sc[k], s[k].w * sc[k]);
        red_add_v4(g_user_new + (size_t)roff[k] * C + q, v);
    }
}

// ---------------------------------------------------------------------------
// merged norm + accumulate + re-zero. One warp per row, float2 per lane.
// rows [0,NE): entity  |  [NE,NE+NN): node  |  [NE+NN,NE+NN+NU): user
// ---------------------------------------------------------------------------
__device__ __forceinline__ float warp_sum(float s) {
    #pragma unroll
    for (int o = 16; o; o >>= 1) s += __shfl_xor_sync(0xffffffffu, s, o);
    return s;
}

__global__ void __launch_bounds__(256) norm_kernel(float* __restrict__ user_res,
                                                   float* __restrict__ node_res,
                                                   float* __restrict__ ent_out) {
    int row  = blockIdx.x * (blockDim.x >> 5) + (threadIdx.x >> 5);
    int lane = threadIdx.x & 31;
    const float2 z2 = make_float2(0.f, 0.f);

    if (row < NE) {
        // entity: l2norm(ent_agg) (count cancels under l2norm)
        size_t idx = (size_t)row * C + lane * 2;
        float2 v = *(const float2*)(g_agg + idx);
        *(float2*)(g_agg + idx) = z2;
        float s = warp_sum(v.x * v.x + v.y * v.y);
        float inv = 1.0f / fmaxf(sqrtf(s), 1e-12f);
        float2 o = make_float2(v.x * inv, v.y * inv);
        *(float2*)(g_all + (size_t)(NU + row) * C + lane * 2) = o;
        if (ent_out) *(float2*)(ent_out + idx) = o;
    } else if (row < NE + NN) {
        // node: l2norm(node_agg); store user half as next-hop gather src
        int r = row - NE;
        size_t aidx = (size_t)row * C + lane * 2;
        float2 v = *(const float2*)(g_agg + aidx);
        *(float2*)(g_agg + aidx) = z2;
        float s = warp_sum(v.x * v.x + v.y * v.y);
        float inv = 1.0f / fmaxf(sqrtf(s), 1e-12f);
        float2 o = make_float2(v.x * inv, v.y * inv);
        size_t ridx = (size_t)r * C + lane * 2;
        if (r < NU) *(float2*)(g_all + ridx) = o;
        float2 acc = *(const float2*)(node_res + ridx);
        acc.x += o.x; acc.y += o.y;
        *(float2*)(node_res + ridx) = acc;
    } else if (row < NE + NN + NU) {
        // user: user_res += l2norm(user_new)
        int r = row - NE - NN;
        size_t idx = (size_t)r * C + lane * 2;
        float2 v = *(const float2*)(g_user_new + idx);
        *(float2*)(g_user_new + idx) = z2;
        float s = warp_sum(v.x * v.x + v.y * v.y);
        float inv = 1.0f / fmaxf(sqrtf(s), 1e-12f);
        float2 acc = *(const float2*)(user_res + idx);
        acc.x += v.x * inv; acc.y += v.y * inv;
        *(float2*)(user_res + idx) = acc;
    }
}

// ---------------------------------------------------------------------------
extern "C" void kernel_launch(void* const* d_in, const int* in_sizes, int n_in,
                              void* d_out, int out_size) {
    const float* user_emb     = (const float*)d_in[0];
    const float* entity_emb   = (const float*)d_in[1];
    const float* weight       = (const float*)d_in[2];
    const float* extra_weight = (const float*)d_in[3];
    const float* im_val       = (const float*)d_in[4];
    const int*   edge_index   = (const int*)d_in[5];
    const int*   edge_type    = (const int*)d_in[6];
    const int*   extra_eidx   = (const int*)d_in[7];
    const int*   extra_etype  = (const int*)d_in[8];
    const int*   im_row       = (const int*)d_in[9];
    const int*   im_col       = (const int*)d_in[10];

    const int E   = in_sizes[6];
    const int E2  = in_sizes[8];
    const int NNZ = in_sizes[4];

    float* out      = (float*)d_out;
    float* user_res = out;                      // [NU, C]
    float* ent_out  = out + (size_t)NU * C;     // [NE, C] final entity_emb
    float* node_res = out + (size_t)NN * C;     // [NN, C]

    init_kernel<<<2048, 256>>>(user_emb, entity_emb, out);
    cnt_kernel<<<(E + 255) / 256, 256>>>(edge_index, E);
    scale_kernel<<<(NNZ + 255) / 256, 256>>>(im_val, im_col, NNZ);

    const int total_edges = E + E2;
    const int edge_groups = (total_edges + 3) / 4;
    const int edge_blocks = (edge_groups * 16 + 255) / 256;
    const int im_groups   = (NNZ + 3) / 4;
    const int im_blocks   = (im_groups * 16 + 255) / 256;
    const int norm_rows   = NE + NN + NU;
    const int norm_blocks = (norm_rows + 7) / 8;

    for (int hop = 0; hop < N_HOPS; hop++) {
        edge_kernel<<<edge_blocks, 256>>>(edge_index, edge_type,
                                          extra_eidx, extra_etype,
                                          weight, extra_weight, E, E2);
        im_kernel<<<im_blocks, 256>>>(im_row, im_col, NNZ);
        norm_kernel<<<norm_blocks, 256>>>(user_res, node_res,
                                          hop == N_HOPS - 1 ? ent_out : nullptr);
    }
}

// round 4
// speedup vs baseline: 2.2320x; 2.1511x over previous
#include <cuda_runtime.h>

#define NU 100000          // n_users
#define NE 100000          // n_entities
#define NN 200000          // n_nodes
#define C  64              // channels
#define N_HOPS 3

// -------- persistent scratch (static device globals; no allocation) --------
__device__ __align__(16) float g_all[(size_t)NN * C];          // gather source: [users ; entities]
__device__ __align__(16) float g_agg[(size_t)(NE + NN) * C];   // [ent_agg ; node_agg]
__device__ __align__(16) float g_user_new[(size_t)NU * C];
__device__ __align__(16) float g_ent_cnt[NE];
__device__ __align__(16) float g_im_scale[1000000];

__device__ __forceinline__ void red_add_v4(float* addr, float4 v) {
    asm volatile("red.global.add.v4.f32 [%0], {%1, %2, %3, %4};"
                 :: "l"(addr), "f"(v.x), "f"(v.y), "f"(v.z), "f"(v.w)
                 : "memory");
}

// ---------------------------------------------------------------------------
// init: g_all = [user_emb ; entity_emb]; out.user_res = user_emb;
//       out.node_res = [user_emb ; entity_emb]; zero g_ent_cnt
// ---------------------------------------------------------------------------
__global__ void init_kernel(const float* __restrict__ user_emb,
                            const float* __restrict__ entity_emb,
                            float* __restrict__ out) {
    const size_t nn4   = (size_t)NN * C / 4;
    const size_t nu4   = (size_t)NU * C / 4;
    const size_t total = nn4 + NE / 4;
    const float4 z = make_float4(0.f, 0.f, 0.f, 0.f);
    float4*       all4 = (float4*)g_all;
    const float4* ue4  = (const float4*)user_emb;
    const float4* ee4  = (const float4*)entity_emb;
    float4*       out4 = (float4*)out;
    for (size_t i = (size_t)blockIdx.x * blockDim.x + threadIdx.x;
         i < total; i += (size_t)gridDim.x * blockDim.x) {
        if (i < nn4) {
            float4 v;
            if (i < nu4) { v = ue4[i]; out4[i] = v; }        // user_res init
            else         { v = ee4[i - nu4]; }
            all4[i] = v;
            out4[nn4 + i] = v;                               // node_res init
        } else {
            ((float4*)g_ent_cnt)[i - nn4] = z;
        }
    }
}

// counts are hop-invariant: compute once
__global__ void cnt_kernel(const int* __restrict__ ei, int E) {
    int e = blockIdx.x * blockDim.x + threadIdx.x;
    if (e < E) atomicAdd(g_ent_cnt + ei[e], 1.0f);
}

// im scale is hop-invariant: scale[e] = im_val[e] / max(cnt[col[e]], 1)
__global__ void scale_kernel(const float* __restrict__ im_val,
                             const int* __restrict__ im_col, int NNZ) {
    int e = blockIdx.x * blockDim.x + threadIdx.x;
    if (e < NNZ)
        g_im_scale[e] = im_val[e] / fmaxf(g_ent_cnt[im_col[e]], 1.0f);
}

// per-hop zero of accumulators (pure streaming float4 stores)
__global__ void zero_kernel() {
    const size_t t1 = (size_t)(NE + NN) * C / 4;     // g_agg
    const size_t t2 = t1 + (size_t)NU * C / 4;       // g_user_new
    const float4 z = make_float4(0.f, 0.f, 0.f, 0.f);
    for (size_t i = (size_t)blockIdx.x * blockDim.x + threadIdx.x;
         i < t2; i += (size_t)gridDim.x * blockDim.x) {
        if (i < t1) ((float4*)g_agg     )[i]      = z;
        else        ((float4*)g_user_new)[i - t1] = z;
    }
}

// ---------------------------------------------------------------------------
// merged edge scatter (4 edges per thread, 16 threads per edge) — proven fast
//   e <  E : g_agg[head]    += g_all[NU+tail] * weight[type-1]
//   e >= E : g_agg[NE + eh] += g_all[et]      * extra_weight[type]
// ---------------------------------------------------------------------------
__global__ void __launch_bounds__(256) edge_kernel(
    const int* __restrict__ ei,  const int* __restrict__ ety,
    const int* __restrict__ e2i, const int* __restrict__ e2ty,
    const float* __restrict__ w, const float* __restrict__ w2,
    int E, int E2)
{
    int tid  = blockIdx.x * blockDim.x + threadIdx.x;
    int g    = tid >> 4;
    int q    = (tid & 15) * 4;
    int base = g * 4;
    int total = E + E2;
    if (base >= total) return;

    int  soff[4], doff[4];
    const float* wp[4];
    bool valid[4];
    #pragma unroll
    for (int k = 0; k < 4; k++) {
        int e = base + k;
        valid[k] = (e < total);
        soff[k] = 0; doff[k] = 0; wp[k] = w;
        if (!valid[k]) continue;
        if (e < E) {
            soff[k] = NU + ei[E + e];                  // tail
            doff[k] = ei[e];                           // head
            wp[k]   = w + (size_t)(ety[e] - 1) * C;
        } else {
            int e2  = e - E;
            soff[k] = e2i[E2 + e2];                    // et
            doff[k] = NE + e2i[e2];                    // eh
            wp[k]   = w2 + (size_t)e2ty[e2] * C;
        }
    }

    float4 s[4], wv[4];
    #pragma unroll
    for (int k = 0; k < 4; k++) if (valid[k]) {
        s[k]  = *(const float4*)(g_all + (size_t)soff[k] * C + q);
        wv[k] = __ldg((const float4*)(wp[k] + q));
    }
    #pragma unroll
    for (int k = 0; k < 4; k++) if (valid[k]) {
        float4 v = make_float4(s[k].x * wv[k].x, s[k].y * wv[k].y,
                               s[k].z * wv[k].z, s[k].w * wv[k].w);
        red_add_v4(g_agg + (size_t)doff[k] * C + q, v);
    }
}

// ---------------------------------------------------------------------------
// implicit-matrix user aggregation (4 nnz per thread):
//   user_new[r] += ent_agg[c] * precomputed_scale[e]
// ---------------------------------------------------------------------------
__global__ void __launch_bounds__(256) im_kernel(
    const int* __restrict__ im_row, const int* __restrict__ im_col, int NNZ)
{
    int tid  = blockIdx.x * blockDim.x + threadIdx.x;
    int g    = tid >> 4;
    int q    = (tid & 15) * 4;
    int base = g * 4;
    if (base >= NNZ) return;

    int   coff[4], roff[4];
    float sc[4];
    bool  valid[4];
    #pragma unroll
    for (int k = 0; k < 4; k++) {
        int e = base + k;
        valid[k] = (e < NNZ);
        coff[k] = 0; roff[k] = 0; sc[k] = 0.f;
        if (!valid[k]) continue;
        roff[k] = im_row[e];
        coff[k] = im_col[e];
        sc[k]   = g_im_scale[e];
    }
    float4 s[4];
    #pragma unroll
    for (int k = 0; k < 4; k++) if (valid[k])
        s[k] = *(const float4*)(g_agg + (size_t)coff[k] * C + q);
    #pragma unroll
    for (int k = 0; k < 4; k++) if (valid[k]) {
        float4 v = make_float4(s[k].x * sc[k], s[k].y * sc[k],
                               s[k].z * sc[k], s[k].w * sc[k]);
        red_add_v4(g_user_new + (size_t)roff[k] * C + q, v);
    }
}

// ---------------------------------------------------------------------------
// split norm kernels (R1 structure — known fast). One warp per row.
// ---------------------------------------------------------------------------
__device__ __forceinline__ float warp_sum(float s) {
    #pragma unroll
    for (int o = 16; o; o >>= 1) s += __shfl_xor_sync(0xffffffffu, s, o);
    return s;
}

// entity: l2norm(ent_agg) (mean divide cancels) -> g_all entity half (+ent_out last hop)
__global__ void __launch_bounds__(256) ent_norm_kernel(float* __restrict__ ent_out) {
    int row = blockIdx.x * (blockDim.x >> 5) + (threadIdx.x >> 5);
    if (row >= NE) return;
    int lane = threadIdx.x & 31;
    size_t idx = (size_t)row * C + lane * 2;
    float2 v = *(const float2*)(g_agg + idx);
    float s = warp_sum(v.x * v.x + v.y * v.y);
    float inv = 1.0f / fmaxf(sqrtf(s), 1e-12f);
    float2 o = make_float2(v.x * inv, v.y * inv);
    *(float2*)(g_all + (size_t)(NU + row) * C + lane * 2) = o;
    if (ent_out) *(float2*)(ent_out + idx) = o;
}

// node: l2norm(node_agg); node_res += ; user half -> g_all
__global__ void __launch_bounds__(256) node_norm_kernel(float* __restrict__ res) {
    int row = blockIdx.x * (blockDim.x >> 5) + (threadIdx.x >> 5);
    if (row >= NN) return;
    int lane = threadIdx.x & 31;
    size_t aidx = (size_t)(NE + row) * C + lane * 2;
    float2 v = *(const float2*)(g_agg + aidx);
    float s = warp_sum(v.x * v.x + v.y * v.y);
    float inv = 1.0f / fmaxf(sqrtf(s), 1e-12f);
    float2 o = make_float2(v.x * inv, v.y * inv);
    size_t ridx = (size_t)row * C + lane * 2;
    if (row < NU) *(float2*)(g_all + ridx) = o;
    float2 acc = *(const float2*)(res + ridx);
    acc.x += o.x; acc.y += o.y;
    *(float2*)(res + ridx) = acc;
}

// user: user_res += l2norm(user_new)
__global__ void __launch_bounds__(256) user_norm_kernel(float* __restrict__ res) {
    int row = blockIdx.x * (blockDim.x >> 5) + (threadIdx.x >> 5);
    if (row >= NU) return;
    int lane = threadIdx.x & 31;
    size_t idx = (size_t)row * C + lane * 2;
    float2 v = *(const float2*)(g_user_new + idx);
    float s = warp_sum(v.x * v.x + v.y * v.y);
    float inv = 1.0f / fmaxf(sqrtf(s), 1e-12f);
    float2 acc = *(const float2*)(res + idx);
    acc.x += v.x * inv; acc.y += v.y * inv;
    *(float2*)(res + idx) = acc;
}

// ---------------------------------------------------------------------------
extern "C" void kernel_launch(void* const* d_in, const int* in_sizes, int n_in,
                              void* d_out, int out_size) {
    const float* user_emb     = (const float*)d_in[0];
    const float* entity_emb   = (const float*)d_in[1];
    const float* weight       = (const float*)d_in[2];
    const float* extra_weight = (const float*)d_in[3];
    const float* im_val       = (const float*)d_in[4];
    const int*   edge_index   = (const int*)d_in[5];
    const int*   edge_type    = (const int*)d_in[6];
    const int*   extra_eidx   = (const int*)d_in[7];
    const int*   extra_etype  = (const int*)d_in[8];
    const int*   im_row       = (const int*)d_in[9];
    const int*   im_col       = (const int*)d_in[10];

    const int E   = in_sizes[6];
    const int E2  = in_sizes[8];
    const int NNZ = in_sizes[4];

    float* out      = (float*)d_out;
    float* user_res = out;                      // [NU, C]
    float* ent_out  = out + (size_t)NU * C;     // [NE, C] final entity_emb
    float* node_res = out + (size_t)NN * C;     // [NN, C]

    init_kernel<<<2048, 256>>>(user_emb, entity_emb, out);
    cnt_kernel<<<(E + 255) / 256, 256>>>(edge_index, E);
    scale_kernel<<<(NNZ + 255) / 256, 256>>>(im_val, im_col, NNZ);

    const int total_edges = E + E2;
    const int edge_groups = (total_edges + 3) / 4;
    const int edge_blocks = (edge_groups * 16 + 255) / 256;
    const int im_groups   = (NNZ + 3) / 4;
    const int im_blocks   = (im_groups * 16 + 255) / 256;

    for (int hop = 0; hop < N_HOPS; hop++) {
        zero_kernel<<<2048, 256>>>();
        edge_kernel<<<edge_blocks, 256>>>(edge_index, edge_type,
                                          extra_eidx, extra_etype,
                                          weight, extra_weight, E, E2);
        im_kernel<<<im_blocks, 256>>>(im_row, im_col, NNZ);
        ent_norm_kernel<<<(NE + 7) / 8, 256>>>(hop == N_HOPS - 1 ? ent_out : nullptr);
        node_norm_kernel<<<(NN + 7) / 8, 256>>>(node_res);
        user_norm_kernel<<<(NU + 7) / 8, 256>>>(user_res);
    }
}

// round 5
// speedup vs baseline: 3.3218x; 1.4882x over previous
#include <cuda_runtime.h>

#define NU 100000
#define NE 100000
#define NN 200000
#define C  64
#define N_HOPS 3
#define NT (NE + NN + NU)            // combined destination space
#define MAXREC 4000000               // E + E2 + NNZ
#define SCAN_BLK 1024
#define NB ((NT + SCAN_BLK - 1) / SCAN_BLK)

// -------- persistent scratch (static device globals) --------
__device__ __align__(16) float g_all0[(size_t)NN * C];   // ping
__device__ __align__(16) float g_all1[(size_t)NN * C];   // pong
__device__ __align__(16) float g_w[31 * C];              // combined weight tables
__device__ __align__(16) float g_f[NE];                  // per-hop ||sum||/cnt
__device__ int  g_cnt[NT];
__device__ int  g_rowptr[NT + 1];
__device__ int  g_cursor[NT];
__device__ int  g_blocksums[NB];
__device__ __align__(16) int2 g_rec[MAXREC];

// ---------------------------------------------------------------------------
__global__ void init_kernel(const float* __restrict__ user_emb,
                            const float* __restrict__ entity_emb,
                            const float* __restrict__ w,
                            const float* __restrict__ w2,
                            float* __restrict__ out) {
    const size_t nn4   = (size_t)NN * C / 4;
    const size_t nu4   = (size_t)NU * C / 4;
    const size_t cnt_n = NT;
    const size_t total = nn4 + cnt_n + 31 * C;
    float4*       all4 = (float4*)g_all0;
    const float4* ue4  = (const float4*)user_emb;
    const float4* ee4  = (const float4*)entity_emb;
    float4*       out4 = (float4*)out;
    for (size_t i = (size_t)blockIdx.x * blockDim.x + threadIdx.x;
         i < total; i += (size_t)gridDim.x * blockDim.x) {
        if (i < nn4) {
            float4 v;
            if (i < nu4) { v = ue4[i]; out4[i] = v; }      // user_res init
            else         { v = ee4[i - nu4]; }
            all4[i] = v;
            out4[nn4 + i] = v;                             // node_res init
        } else if (i < nn4 + cnt_n) {
            g_cnt[i - nn4] = 0;
        } else {
            size_t j = i - nn4 - cnt_n;
            g_w[j] = (j < 15 * C) ? w[j] : w2[j - 15 * C];
        }
    }
}

// ---------------------------------------------------------------------------
// CSR build (one-time)
// dest space: [0,NE): entity edges | [NE,NE+NN): node edges | [NE+NN,NT): im
// ---------------------------------------------------------------------------
__global__ void hist_kernel(const int* __restrict__ ei,
                            const int* __restrict__ e2i,
                            const int* __restrict__ im_row,
                            int E, int E2, int NNZ) {
    int i = blockIdx.x * blockDim.x + threadIdx.x;
    int total = E + E2 + NNZ;
    if (i >= total) return;
    int d;
    if (i < E)           d = ei[i];
    else if (i < E + E2) d = NE + e2i[i - E];
    else                 d = NE + NN + im_row[i - E - E2];
    atomicAdd(g_cnt + d, 1);
}

__global__ void scan1_kernel() {
    __shared__ int s[256];
    int tid  = threadIdx.x;
    int base = blockIdx.x * SCAN_BLK + tid * 4;
    int v[4], t = 0;
    #pragma unroll
    for (int k = 0; k < 4; k++) {
        v[k] = (base + k < NT) ? g_cnt[base + k] : 0;
        t += v[k];
    }
    s[tid] = t;
    __syncthreads();
    #pragma unroll
    for (int off = 1; off < 256; off <<= 1) {
        int x = (tid >= off) ? s[tid - off] : 0;
        __syncthreads();
        s[tid] += x;
        __syncthreads();
    }
    int excl = s[tid] - t;
    if (tid == 255) g_blocksums[blockIdx.x] = s[255];
    int run = excl;
    #pragma unroll
    for (int k = 0; k < 4; k++) {
        if (base + k < NT) g_rowptr[base + k] = run;
        run += v[k];
    }
}

__global__ void scan2_kernel() {
    if (threadIdx.x == 0 && blockIdx.x == 0) {
        int run = 0;
        for (int i = 0; i < NB; i++) {
            int t = g_blocksums[i];
            g_blocksums[i] = run;
            run += t;
        }
    }
}

__global__ void scan3_kernel(int total_rec) {
    int i = blockIdx.x * blockDim.x + threadIdx.x;
    if (i < NT) {
        int v = g_rowptr[i] + g_blocksums[i / SCAN_BLK];
        g_rowptr[i] = v;
        g_cursor[i] = v;
    }
    if (i == 0) g_rowptr[NT] = total_rec;
}

__global__ void fill_kernel(const int* __restrict__ ei,  const int* __restrict__ ety,
                            const int* __restrict__ e2i, const int* __restrict__ e2ty,
                            const int* __restrict__ im_row, const int* __restrict__ im_col,
                            const float* __restrict__ im_val,
                            int E, int E2, int NNZ) {
    int i = blockIdx.x * blockDim.x + threadIdx.x;
    int total = E + E2 + NNZ;
    if (i >= total) return;
    int d; int2 rec;
    if (i < E) {
        d     = ei[i];
        rec.x = NU + ei[E + i];            // src row (entity half of g_all)
        rec.y = ety[i] - 1;                // weight row 0..14
    } else if (i < E + E2) {
        int e2 = i - E;
        d     = NE + e2i[e2];
        rec.x = e2i[E2 + e2];              // src row (node space)
        rec.y = 15 + e2ty[e2];             // weight row 15..30
    } else {
        int j = i - E - E2;
        d     = NE + NN + im_row[j];
        rec.x = im_col[j];                 // entity col
        rec.y = __float_as_int(im_val[j]); // raw im value
    }
    int pos = atomicAdd(g_cursor + d, 1);
    g_rec[pos] = rec;
}

// ---------------------------------------------------------------------------
// per-hop gathers: 16-lane group per destination row, float4 per lane
// ---------------------------------------------------------------------------
__device__ __forceinline__ float grp_sum16(float s) {
    #pragma unroll
    for (int o = 8; o; o >>= 1) s += __shfl_xor_sync(0xffffffffu, s, o);
    return s;
}

__global__ void __launch_bounds__(256) gather_kernel(
    int flip, float* __restrict__ node_res, float* __restrict__ ent_out)
{
    const float* prev = flip ? g_all1 : g_all0;
    float*       next = flip ? g_all0 : g_all1;

    int gidx = (blockIdx.x * blockDim.x + threadIdx.x) >> 4;
    int lane = threadIdx.x & 15;
    if (gidx >= NE + NN) return;
    int start = g_rowptr[gidx], end = g_rowptr[gidx + 1];

    float4 acc = make_float4(0.f, 0.f, 0.f, 0.f);
    int e = start;
    for (; e + 1 < end; e += 2) {
        int2 r0 = __ldg(g_rec + e);
        int2 r1 = __ldg(g_rec + e + 1);
        float4 s0 = *((const float4*)(prev + (size_t)r0.x * C) + lane);
        float4 s1 = *((const float4*)(prev + (size_t)r1.x * C) + lane);
        float4 w0 = *((const float4*)(g_w + r0.y * C) + lane);
        float4 w1 = *((const float4*)(g_w + r1.y * C) + lane);
        acc.x += s0.x * w0.x + s1.x * w1.x;
        acc.y += s0.y * w0.y + s1.y * w1.y;
        acc.z += s0.z * w0.z + s1.z * w1.z;
        acc.w += s0.w * w0.w + s1.w * w1.w;
    }
    if (e < end) {
        int2 r0 = __ldg(g_rec + e);
        float4 s0 = *((const float4*)(prev + (size_t)r0.x * C) + lane);
        float4 w0 = *((const float4*)(g_w + r0.y * C) + lane);
        acc.x += s0.x * w0.x; acc.y += s0.y * w0.y;
        acc.z += s0.z * w0.z; acc.w += s0.w * w0.w;
    }

    float ss = grp_sum16(acc.x * acc.x + acc.y * acc.y + acc.z * acc.z + acc.w * acc.w);
    float n  = sqrtf(ss);
    float inv = 1.0f / fmaxf(n, 1e-12f);
    float4 o = make_float4(acc.x * inv, acc.y * inv, acc.z * inv, acc.w * inv);

    if (gidx < NE) {
        *((float4*)(next + (size_t)(NU + gidx) * C) + lane) = o;
        if (lane == 0) g_f[gidx] = n / fmaxf((float)(end - start), 1.0f);
        if (ent_out) *((float4*)(ent_out + (size_t)gidx * C) + lane) = o;
    } else {
        int r = gidx - NE;
        if (r < NU) *((float4*)(next + (size_t)r * C) + lane) = o;
        float4* rp = (float4*)(node_res + (size_t)r * C) + lane;
        float4 a = *rp;
        a.x += o.x; a.y += o.y; a.z += o.z; a.w += o.w;
        *rp = a;
    }
}

__global__ void __launch_bounds__(256) im_gather_kernel(
    int flip, float* __restrict__ user_res)
{
    const float* next = flip ? g_all0 : g_all1;   // the buffer just written

    int gidx = (blockIdx.x * blockDim.x + threadIdx.x) >> 4;
    int lane = threadIdx.x & 15;
    if (gidx >= NU) return;
    int row = NE + NN + gidx;
    int start = g_rowptr[row], end = g_rowptr[row + 1];

    float4 acc = make_float4(0.f, 0.f, 0.f, 0.f);
    int e = start;
    for (; e + 1 < end; e += 2) {
        int2 r0 = __ldg(g_rec + e);
        int2 r1 = __ldg(g_rec + e + 1);
        float c0 = __int_as_float(r0.y) * __ldg(g_f + r0.x);
        float c1 = __int_as_float(r1.y) * __ldg(g_f + r1.x);
        float4 s0 = *((const float4*)(next + (size_t)(NU + r0.x) * C) + lane);
        float4 s1 = *((const float4*)(next + (size_t)(NU + r1.x) * C) + lane);
        acc.x += s0.x * c0 + s1.x * c1;
        acc.y += s0.y * c0 + s1.y * c1;
        acc.z += s0.z * c0 + s1.z * c1;
        acc.w += s0.w * c0 + s1.w * c1;
    }
    if (e < end) {
        int2 r0 = __ldg(g_rec + e);
        float c0 = __int_as_float(r0.y) * __ldg(g_f + r0.x);
        float4 s0 = *((const float4*)(next + (size_t)(NU + r0.x) * C) + lane);
        acc.x += s0.x * c0; acc.y += s0.y * c0;
        acc.z += s0.z * c0; acc.w += s0.w * c0;
    }

    float ss = grp_sum16(acc.x * acc.x + acc.y * acc.y + acc.z * acc.z + acc.w * acc.w);
    float inv = 1.0f / fmaxf(sqrtf(ss), 1e-12f);
    float4* rp = (float4*)(user_res + (size_t)gidx * C) + lane;
    float4 a = *rp;
    a.x += acc.x * inv; a.y += acc.y * inv;
    a.z += acc.z * inv; a.w += acc.w * inv;
    *rp = a;
}

// ---------------------------------------------------------------------------
extern "C" void kernel_launch(void* const* d_in, const int* in_sizes, int n_in,
                              void* d_out, int out_size) {
    const float* user_emb     = (const float*)d_in[0];
    const float* entity_emb   = (const float*)d_in[1];
    const float* weight       = (const float*)d_in[2];
    const float* extra_weight = (const float*)d_in[3];
    const int*   edge_index   = (const int*)d_in[5];
    const int*   edge_type    = (const int*)d_in[6];
    const int*   extra_eidx   = (const int*)d_in[7];
    const int*   extra_etype  = (const int*)d_in[8];
    const int*   im_row       = (const int*)d_in[9];
    const int*   im_col       = (const int*)d_in[10];
    const float* im_val       = (const float*)d_in[4];

    const int E   = in_sizes[6];
    const int E2  = in_sizes[8];
    const int NNZ = in_sizes[4];
    const int total_rec = E + E2 + NNZ;

    float* out      = (float*)d_out;
    float* user_res = out;                      // [NU, C]
    float* ent_out  = out + (size_t)NU * C;     // [NE, C]
    float* node_res = out + (size_t)NN * C;     // [NN, C]

    init_kernel<<<2048, 256>>>(user_emb, entity_emb, weight, extra_weight, out);
    hist_kernel<<<(total_rec + 255) / 256, 256>>>(edge_index, extra_eidx, im_row, E, E2, NNZ);
    scan1_kernel<<<NB, 256>>>();
    scan2_kernel<<<1, 32>>>();
    scan3_kernel<<<(NT + 255) / 256, 256>>>(total_rec);
    fill_kernel<<<(total_rec + 255) / 256, 256>>>(edge_index, edge_type,
                                                  extra_eidx, extra_etype,
                                                  im_row, im_col, im_val, E, E2, NNZ);

    const int gather_blocks = ((NE + NN) * 16 + 255) / 256;
    const int im_blocks     = (NU * 16 + 255) / 256;

    for (int hop = 0; hop < N_HOPS; hop++) {
        int flip = hop & 1;
        gather_kernel<<<gather_blocks, 256>>>(flip, node_res,
                                              hop == N_HOPS - 1 ? ent_out : nullptr);
        im_gather_kernel<<<im_blocks, 256>>>(flip, user_res);
    }
}